// round 17
// baseline (speedup 1.0000x reference)
#include <cuda_runtime.h>
#include <math.h>

#define NB      2048
#define NENT    8256
#define KAPPA   0.276f
#define PSTRIDE 132   // pair-block stride (f2): == 4 mod 16

__device__ float g_rn[NB];

__device__ __forceinline__ float2 cmul(float2 a, float2 b) {
    return make_float2(a.x * b.x - a.y * b.y, a.x * b.y + a.y * b.x);
}
__device__ __forceinline__ float2 cadd(float2 a, float2 b) {
    return make_float2(a.x + b.x, a.y + b.y);
}
__device__ __forceinline__ float2 csub(float2 a, float2 b) {
    return make_float2(a.x - b.x, a.y - b.y);
}
__device__ __forceinline__ float2 cdiv(float2 a, float2 b) {
    float inv = 1.0f / (b.x * b.x + b.y * b.y);
    return make_float2((a.x * b.x + a.y * b.y) * inv,
                       (a.y * b.x - a.x * b.y) * inv);
}

// Layout (R9): block p (0..63) at f2 offset 132p:
//   long row 127-p at 132p (len 128-p); short row s(p)=4a+((b-a)&3) (p=4a+b)
//   at 132p+(128-p)+(p&3). All L access streams bank-conflict-free.
__device__ __forceinline__ int short_row_of_block(int p) {
    int a = p >> 2, bq = p & 3;
    return 4 * a + ((bq - a) & 3);
}
__device__ __forceinline__ int block_of_short_row(int s) {
    int a = s >> 2, rho = s & 3;
    return 4 * a + ((a + rho) & 3);
}
__device__ __forceinline__ int short_row_offset(int p) {
    return PSTRIDE * p + (128 - p) + (p & 3);
}

// ---------- w = L * v : shuffle-delivered v ----------
__device__ __forceinline__ void matvecW(float2* __restrict__ wout,
                                        const float2* __restrict__ vin,
                                        const float2* __restrict__ LP,
                                        int p, int q, int s, int lane, int w8) {
    const float2* Lr = LP + PSTRIDE * p;
    const float2* Sr = LP + short_row_offset(p);
    int lim = 127 - p;
    int limW = 127 - 8 * w8;
    int smaxW = 8 * w8 + 7;
    float2 as = make_float2(0.f, 0.f), ar = make_float2(0.f, 0.f);
    #pragma unroll
    for (int m = 0; m < 4; m++) {
        int c0 = m << 5;
        if (c0 > limW) break;                       // uniform
        float2 vblk = vin[c0 + lane];               // 1 coalesced wavefront
        #pragma unroll
        for (int kk = 0; kk < 8; kk++) {
            int src = q + (kk << 2);
            float vx = __shfl_sync(0xffffffffu, vblk.x, src);
            float vy = __shfl_sync(0xffffffffu, vblk.y, src);
            int c = c0 + src;
            if (c <= lim) {
                float2 l = Lr[c];
                as.x = fmaf(l.x, vx, fmaf(-l.y, vy, as.x));
                as.y = fmaf(l.x, vy, fmaf( l.y, vx, as.y));
            }
        }
        if (c0 <= smaxW) {                           // uniform
            #pragma unroll
            for (int kk = 0; kk < 8; kk++) {
                int src = q + (kk << 2);
                float vx = __shfl_sync(0xffffffffu, vblk.x, src);
                float vy = __shfl_sync(0xffffffffu, vblk.y, src);
                int c = c0 + src;
                if (c <= s) {
                    float2 l = Sr[c];
                    ar.x = fmaf(l.x, vx, fmaf(-l.y, vy, ar.x));
                    ar.y = fmaf(l.x, vy, fmaf( l.y, vx, ar.y));
                }
            }
        }
    }
    #pragma unroll
    for (int o = 1; o <= 2; o <<= 1) {
        ar.x += __shfl_xor_sync(0xffffffffu, ar.x, o);
        ar.y += __shfl_xor_sync(0xffffffffu, ar.y, o);
        as.x += __shfl_xor_sync(0xffffffffu, as.x, o);
        as.y += __shfl_xor_sync(0xffffffffu, as.y, o);
    }
    if (q == 0) { wout[s] = ar; wout[127 - p] = as; }
}

// ---------- u = L^H * w with FUSED <r,u> partial dot ----------
// After the xor-reduction all 4 lanes hold ac/ac2; q==0 lanes form
// conj(r[c])*z[c] + conj(r[c2])*z[c2] and a stride-4 tree (16/8/4) reduces the
// 8 per-warp groups (q!=0 lanes contribute exact zeros). red[w8] <- warp partial.
__device__ __forceinline__ void matvecU(float2* __restrict__ uout,
                                        const float2* __restrict__ win,
                                        const float2* __restrict__ rvec,
                                        const float2* __restrict__ LP,
                                        float2* __restrict__ red,
                                        int c, int q, int lane, int w8) {
    int c2 = 127 - c;
    float2 ac = make_float2(0.f, 0.f), ac2 = make_float2(0.f, 0.f);
    float2 wblk3 = win[96 + lane];
    float2 wblk2 = win[64 + lane];
    {   // long rows col c: p' = q+4k, k=0..15
        const float2* Lp = LP + q * PSTRIDE + c;
        #pragma unroll
        for (int kk = 0; kk < 8; kk++) {
            int src = 31 - q - (kk << 2);
            float wx = __shfl_sync(0xffffffffu, wblk3.x, src);
            float wy = __shfl_sync(0xffffffffu, wblk3.y, src);
            float2 l = *Lp;
            ac.x = fmaf(l.x, wx, fmaf( l.y, wy, ac.x));
            ac.y = fmaf(l.x, wy, fmaf(-l.y, wx, ac.y));
            Lp += 4 * PSTRIDE;
        }
        #pragma unroll
        for (int kk = 0; kk < 8; kk++) {
            int src = 31 - q - (kk << 2);
            float wx = __shfl_sync(0xffffffffu, wblk2.x, src);
            float wy = __shfl_sync(0xffffffffu, wblk2.y, src);
            float2 l = *Lp;
            ac.x = fmaf(l.x, wx, fmaf( l.y, wy, ac.x));
            ac.y = fmaf(l.x, wy, fmaf(-l.y, wx, ac.y));
            Lp += 4 * PSTRIDE;
        }
    }
    {   // complement column c2: p' = q..c step 4, tail predicated
        const float2* Lp = LP + q * PSTRIDE + c2;
        #pragma unroll
        for (int m = 0; m < 2; m++) {
            if ((m << 5) > 8 * w8 + 7) break;     // uniform
            #pragma unroll
            for (int kk = 0; kk < 8; kk++) {
                int src = 31 - q - (kk << 2);
                float wx = (m == 0) ? __shfl_sync(0xffffffffu, wblk3.x, src)
                                    : __shfl_sync(0xffffffffu, wblk2.x, src);
                float wy = (m == 0) ? __shfl_sync(0xffffffffu, wblk3.y, src)
                                    : __shfl_sync(0xffffffffu, wblk2.y, src);
                int pp = (m << 5) + q + (kk << 2);
                if (pp <= c) {
                    float2 l = *Lp;
                    ac2.x = fmaf(l.x, wx, fmaf( l.y, wy, ac2.x));
                    ac2.y = fmaf(l.x, wy, fmaf(-l.y, wx, ac2.y));
                }
                Lp += 4 * PSTRIDE;
            }
        }
    }
    {   // short rows s = c+q .. 63 step 4
        #pragma unroll 2
        for (int s = c + q; s <= 63; s += 4) {
            int p2 = block_of_short_row(s);
            float2 l = LP[short_row_offset(p2) + c];
            float2 ws = win[s];
            ac.x = fmaf(l.x, ws.x, fmaf( l.y, ws.y, ac.x));
            ac.y = fmaf(l.x, ws.y, fmaf(-l.y, ws.x, ac.y));
        }
    }
    #pragma unroll
    for (int o = 1; o <= 2; o <<= 1) {
        ac.x  += __shfl_xor_sync(0xffffffffu, ac.x,  o);
        ac.y  += __shfl_xor_sync(0xffffffffu, ac.y,  o);
        ac2.x += __shfl_xor_sync(0xffffffffu, ac2.x, o);
        ac2.y += __shfl_xor_sync(0xffffffffu, ac2.y, o);
    }
    // fused partial dot <r, u>
    float2 dc = make_float2(0.f, 0.f);
    if (q == 0) {
        uout[c] = ac;
        uout[c2] = ac2;
        float2 rc = rvec[c], rc2 = rvec[c2];
        dc.x = rc.x * ac.x + rc.y * ac.y + rc2.x * ac2.x + rc2.y * ac2.y;
        dc.y = rc.x * ac.y - rc.y * ac.x + rc2.x * ac2.y - rc2.y * ac2.x;
    }
    #pragma unroll
    for (int o = 16; o >= 4; o >>= 1) {
        dc.x += __shfl_down_sync(0xffffffffu, dc.x, o);
        dc.y += __shfl_down_sync(0xffffffffu, dc.y, o);
    }
    if (lane == 0) red[w8] = dc;
}

// ---------- Wilson-Dirac stencil, 128-thread form ----------
__device__ __forceinline__ float2 dirac_site(const float2* __restrict__ in,
                                             const float2* __restrict__ Us,
                                             float g, int t) {
    int st = t >> 1, sp = t & 1;
    int x = st >> 3, y = st & 7;
    float sg = (sp == 0) ? g : -g;
    float2 a = in[t];
    float2 acc = make_float2(0.f, 0.f);
    {   // mu = 0 (sigma_x)
        int spx = (((x + 1) & 7) << 3) | y;
        int smx = (((x + 7) & 7) << 3) | y;
        float2 u  = Us[st];
        float2 ub = Us[smx]; ub.y = -ub.y;
        float2 fs = cmul(u,  in[2 * spx + sp]);
        float2 fo = cmul(u,  in[2 * spx + 1 - sp]);
        float2 bs = cmul(ub, in[2 * smx + sp]);
        float2 bo = cmul(ub, in[2 * smx + 1 - sp]);
        acc.x += fs.x - g * fo.x + bs.x + g * bo.x;
        acc.y += fs.y - g * fo.y + bs.y + g * bo.y;
    }
    {   // mu = 1 (sigma_y)
        int spy = (x << 3) | ((y + 1) & 7);
        int smy = (x << 3) | ((y + 7) & 7);
        float2 u  = Us[64 + st];
        float2 ub = Us[64 + smy]; ub.y = -ub.y;
        float2 fs = cmul(u,  in[2 * spy + sp]);
        float2 fo = cmul(u,  in[2 * spy + 1 - sp]);
        float2 bs = cmul(ub, in[2 * smy + sp]);
        float2 bo = cmul(ub, in[2 * smy + 1 - sp]);
        acc.x += fs.x - sg * fo.y + bs.x + sg * bo.y;
        acc.y += fs.y + sg * fo.x + bs.y - sg * bo.x;
    }
    return make_float2(a.x - KAPPA * acc.x, a.y - KAPPA * acc.y);
}

// ---------- block-wide complex dot (final norm only) ----------
__device__ __forceinline__ float2 dot_all(const float2* __restrict__ a,
                                          const float2* __restrict__ c,
                                          float2* __restrict__ red, int off) {
    int tid = threadIdx.x;
    float2 s = make_float2(0.f, 0.f);
    if (tid < 128) {
        float2 av = a[tid], cv = c[tid];
        s.x = av.x * cv.x + av.y * cv.y;
        s.y = av.x * cv.y - av.y * cv.x;
    }
    #pragma unroll
    for (int o = 16; o; o >>= 1) {
        s.x += __shfl_down_sync(0xffffffffu, s.x, o);
        s.y += __shfl_down_sync(0xffffffffu, s.y, o);
    }
    int warp = tid >> 5, lane = tid & 31;
    if (lane == 0 && warp < 4) red[off + warp] = s;
    __syncthreads();
    float2 r0 = red[off], r1 = red[off + 1], r2 = red[off + 2], r3 = red[off + 3];
    return make_float2(r0.x + r1.x + r2.x + r3.x, r0.y + r1.y + r2.y + r3.y);
}

#define LREGION (64 * PSTRIDE)
#define SMEM_F2 (LREGION + 128 + 5 * 128 + 16)   // 73,856 B

__global__ void __launch_bounds__(256, 3)
cg_kernel(const float* __restrict__ nre, const float* __restrict__ nim,
          const float* __restrict__ theta, const float* __restrict__ bglob) {
    extern __shared__ float2 smbuf[];
    float2* LP  = smbuf;
    float2* Us  = LP  + LREGION;
    float2* xv  = Us  + 128;
    float2* rv  = xv  + 128;
    float2* pv  = rv  + 128;
    float2* Apv = pv  + 128;   // also holds z = M(r)
    float2* tv  = Apv + 128;
    float2* red = tv  + 128;   // [0..7] rz partials, [8..11] pAp / final norm

    int b = blockIdx.x, tid = threadIdx.x;
    int warp = tid >> 5, lane = tid & 31;
    int g = lane >> 2, q = lane & 3;
    int p = warp * 8 + g;
    int s = short_row_of_block(p);
    const float* nre_b = nre + (size_t)b * NENT;
    const float* nim_b = nim + (size_t)b * NENT;

    // zero L region (pads read as 0)
    for (int i = tid; i < LREGION; i += 256)
        LP[i] = make_float2(0.f, 0.f);
    __syncthreads();

    // load L into swizzled pair-packed layout
    for (int row = warp; row < 128; row += 8) {
        int base = (row * (row + 1)) >> 1;
        int off;
        if (row >= 64) off = PSTRIDE * (127 - row);
        else           off = short_row_offset(block_of_short_row(row));
        for (int cc = lane; cc <= row; cc += 32)
            LP[off + cc] = make_float2(nre_b[base + cc], nim_b[base + cc]);
    }

    if (tid < 128) {
        float th = theta[(size_t)b * 128 + tid];
        float sn, cs;
        sincosf(th, &sn, &cs);
        Us[tid] = make_float2(cs, sn);
        float bb = bglob[(size_t)b * 128 + tid];
        rv[tid] = make_float2(bb, 0.f);
        xv[tid] = make_float2(0.f, 0.f);
    }
    __syncthreads();

    matvecW(tv, rv, LP, p, q, s, lane, warp); __syncthreads();
    matvecU(Apv, tv, rv, LP, red, p, q, lane, warp); __syncthreads();
    float2 rz;
    {
        float2 t0 = red[0];
        #pragma unroll
        for (int i = 1; i < 8; i++) { t0.x += red[i].x; t0.y += red[i].y; }
        rz = t0;
    }
    if (tid < 128) pv[tid] = Apv[tid];

    for (int it = 0; it < 20; ++it) {
        __syncthreads();                       // pv settled; red reads done
        if (tid < 128) tv[tid] = dirac_site(pv, Us, 1.f, tid);
        if (tid < 128) asm volatile("bar.sync 1, 128;" ::: "memory");
        if (tid < 128) {
            float2 o = dirac_site(tv, Us, -1.f, tid);
            Apv[tid] = o;
            float2 pval = pv[tid];
            float2 sd;
            sd.x = pval.x * o.x + pval.y * o.y;
            sd.y = pval.x * o.y - pval.y * o.x;
            #pragma unroll
            for (int of = 16; of; of >>= 1) {
                sd.x += __shfl_down_sync(0xffffffffu, sd.x, of);
                sd.y += __shfl_down_sync(0xffffffffu, sd.y, of);
            }
            if (lane == 0) red[8 + warp] = sd;
        }
        __syncthreads();
        float2 r8 = red[8], r9 = red[9], r10 = red[10], r11 = red[11];
        float2 pAp = make_float2(r8.x + r9.x + r10.x + r11.x,
                                 r8.y + r9.y + r10.y + r11.y);
        float2 alpha = cdiv(rz, pAp);
        if (tid < 128) {
            xv[tid] = cadd(xv[tid], cmul(alpha, pv[tid]));
            rv[tid] = csub(rv[tid], cmul(alpha, Apv[tid]));
        }
        __syncthreads();
        matvecW(tv, rv, LP, p, q, s, lane, warp); __syncthreads();
        matvecU(Apv, tv, rv, LP, red, p, q, lane, warp); __syncthreads();
        float2 rz2;
        {
            float2 t0 = red[0];
            #pragma unroll
            for (int i = 1; i < 8; i++) { t0.x += red[i].x; t0.y += red[i].y; }
            rz2 = t0;
        }
        float2 beta = cdiv(rz2, rz);
        if (tid < 128)
            pv[tid] = cadd(Apv[tid], cmul(beta, pv[tid]));
        rz = rz2;
    }
    __syncthreads();

    // residual: || A(x) - b ||
    if (tid < 128) tv[tid] = dirac_site(xv, Us, 1.f, tid);
    if (tid < 128) asm volatile("bar.sync 1, 128;" ::: "memory");
    if (tid < 128) {
        float2 o = dirac_site(tv, Us, -1.f, tid);
        float bb = bglob[(size_t)b * 128 + tid];
        Apv[tid] = csub(o, make_float2(bb, 0.f));
    }
    __syncthreads();
    float2 nrm = dot_all(Apv, Apv, red, 8);
    if (tid == 0) g_rn[b] = sqrtf(nrm.x);
}

__global__ void reduce_kernel(float* __restrict__ out) {
    __shared__ float sm[256];
    float s = 0.f;
    for (int i = threadIdx.x; i < NB; i += 256) s += g_rn[i];
    sm[threadIdx.x] = s;
    __syncthreads();
    for (int off = 128; off; off >>= 1) {
        if (threadIdx.x < off) sm[threadIdx.x] += sm[threadIdx.x + off];
        __syncthreads();
    }
    if (threadIdx.x == 0) out[0] = sm[0] * (1.0f / (float)NB);
}

// ncu captures launch index 3: keep 3 nops so idx3 = cg_kernel.
__global__ void nop_kernel() {}

extern "C" void kernel_launch(void* const* d_in, const int* in_sizes, int n_in,
                              void* d_out, int out_size) {
    const float* nre   = (const float*)d_in[0];
    const float* nim   = (const float*)d_in[1];
    const float* theta = (const float*)d_in[2];
    const float* bvec  = (const float*)d_in[3];
    float* out = (float*)d_out;

    size_t smem = (size_t)SMEM_F2 * sizeof(float2);   // 73,856 B -> 3 CTAs/SM
    cudaFuncSetAttribute(cg_kernel, cudaFuncAttributeMaxDynamicSharedMemorySize, (int)smem);
    nop_kernel<<<1, 32>>>();
    nop_kernel<<<1, 32>>>();
    nop_kernel<<<1, 32>>>();
    cg_kernel<<<NB, 256, smem>>>(nre, nim, theta, bvec);
    reduce_kernel<<<1, 256>>>(out);
}